// round 17
// baseline (speedup 1.0000x reference)
#include <cuda_runtime.h>
#include <cuda_fp16.h>
#include <cstdint>
#include <cstddef>

#define BATCH 8192
#define FDIM  4096
#define NINT  511
#define NLEAF 512
#define KOUT  1000

// ---------------- scratch (device globals; no dynamic allocation) ----------
__device__ float  g_ps[(size_t)BATCH * 512];          // sigmoid node probs
__device__ __half g_lp[(size_t)BATCH * 512];          // leaf probs (fp16)
__device__ __half g_dT[(size_t)KOUT * 512];           // dists^T [class][leaf]
__device__ __half g_xs16[(size_t)BATCH * FDIM];       // xs pre-converted fp16
__device__ __half g_W16[(size_t)512 * FDIM];          // W fp16, row 511 zero-padded

// m16n8k16 row.col fp16 -> f32 accumulate (baseline PTX, works on sm_103)
__device__ __forceinline__ void mma16816(float* c, const uint32_t* a, const uint32_t* b) {
    asm volatile(
        "mma.sync.aligned.m16n8k16.row.col.f32.f16.f16.f32 "
        "{%0,%1,%2,%3}, {%4,%5,%6,%7}, {%8,%9}, {%0,%1,%2,%3};\n"
        : "+f"(c[0]), "+f"(c[1]), "+f"(c[2]), "+f"(c[3])
        : "r"(a[0]), "r"(a[1]), "r"(a[2]), "r"(a[3]), "r"(b[0]), "r"(b[1]));
}

#define LDA 40                // fp16/row: 80 B = 20 banks -> conflict-free frag LDS
#define ARR (128 * LDA)       // elements per tile array (5120)

// ============================================================================
// Kernel 0: fp32 -> fp16 conversion (vectorized x8), zero-pad past n_src
// ============================================================================
__global__ void cvt_kernel(const float* __restrict__ src, __half* __restrict__ dst,
                           int n_src, int n_pad) {
    if (src == nullptr) return;  // warmup guard
    int idx = (blockIdx.x * 256 + threadIdx.x) * 8;
    if (idx >= n_pad) return;
    float4 v0, v1;
    if (idx + 8 <= n_src) {
        v0 = *(const float4*)(src + idx);
        v1 = *(const float4*)(src + idx + 4);
    } else {
        v0 = make_float4(0.f, 0.f, 0.f, 0.f);
        v1 = v0;
    }
    __half2 h0 = __floats2half2_rn(v0.x, v0.y);
    __half2 h1 = __floats2half2_rn(v0.z, v0.w);
    __half2 h2 = __floats2half2_rn(v1.x, v1.y);
    __half2 h3 = __floats2half2_rn(v1.z, v1.w);
    uint4 o;
    o.x = *reinterpret_cast<uint32_t*>(&h0);
    o.y = *reinterpret_cast<uint32_t*>(&h1);
    o.z = *reinterpret_cast<uint32_t*>(&h2);
    o.w = *reinterpret_cast<uint32_t*>(&h3);
    *(uint4*)(dst + idx) = o;
}

// ============================================================================
// Kernel 1: dists = softmax(leaf_params, axis=-1), stored transposed fp16
// ============================================================================
__global__ void softmax_kernel(const float* __restrict__ leaf) {
    if (leaf == nullptr) return;  // warmup guard
    int j = blockIdx.x;           // leaf index 0..511
    int tid = threadIdx.x;        // 256 threads
    __shared__ float red[256];

    float v[4];
    float m = -1e30f;
#pragma unroll
    for (int i = 0; i < 4; i++) {
        int k = tid + i * 256;
        v[i] = (k < KOUT) ? leaf[(size_t)j * KOUT + k] : -1e30f;
        m = fmaxf(m, v[i]);
    }
    red[tid] = m; __syncthreads();
    for (int s = 128; s > 0; s >>= 1) { if (tid < s) red[tid] = fmaxf(red[tid], red[tid + s]); __syncthreads(); }
    m = red[0]; __syncthreads();

    float sum = 0.f;
#pragma unroll
    for (int i = 0; i < 4; i++) {
        int k = tid + i * 256;
        if (k < KOUT) { v[i] = __expf(v[i] - m); sum += v[i]; }
    }
    red[tid] = sum; __syncthreads();
    for (int s = 128; s > 0; s >>= 1) { if (tid < s) red[tid] += red[tid + s]; __syncthreads(); }
    float inv = 1.0f / red[0];

#pragma unroll
    for (int i = 0; i < 4; i++) {
        int k = tid + i * 256;
        if (k < KOUT) g_dT[(size_t)k * 512 + j] = __float2half_rn(v[i] * inv);
    }
}

// ============================================================================
// Kernel 2: GEMM1  ps = sigmoid(xs16 @ W16^T + b)
// Single-pass fp16 HMMA; CTA 128x128, K-chunk 32, 8 warps (4x2), warp 32x64.
// fp16 operands from gmem (no in-loop cvt), double-buffered static smem 40KB,
// 2 CTAs/SM via launch_bounds.
// ============================================================================
__global__ void __launch_bounds__(256, 2)
gemm1_kernel(const float* __restrict__ bias) {
    if (bias == nullptr) return;  // warmup guard
    __shared__ __half sm[2][2 * ARR];   // [buf][A | B]

    int tid = threadIdx.x, lane = tid & 31, wid = tid >> 5;
    int wr = wid & 3, wc = wid >> 2;
    int mBase = blockIdx.y * 128, nBase = blockIdx.x * 128;

    float acc[2][8][4];
#pragma unroll
    for (int mt = 0; mt < 2; mt++)
#pragma unroll
        for (int nt = 0; nt < 8; nt++)
#pragma unroll
            for (int i = 0; i < 4; i++) acc[mt][nt][i] = 0.f;

    // A tile 128x32 fp16 = 512 uint4 lines; 256 thr -> 2 A lines + 2 B lines
    const int ld_row = tid >> 2, ld_q = tid & 3;   // rows 0..63 (+64 for i=1)
    uint4 la[2], lb[2];

    auto gload = [&](int k0) {
#pragma unroll
        for (int i = 0; i < 2; i++) {
            int row = ld_row + i * 64;
            la[i] = *(const uint4*)(g_xs16 + (size_t)(mBase + row) * FDIM + k0 + ld_q * 8);
            lb[i] = *(const uint4*)(g_W16  + (size_t)(nBase + row) * FDIM + k0 + ld_q * 8);
        }
    };
    auto sstore = [&](int buf) {
        __half* base = sm[buf];
#pragma unroll
        for (int i = 0; i < 2; i++) {
            int row = ld_row + i * 64;
            *(uint4*)(base + row * LDA + ld_q * 8)       = la[i];
            *(uint4*)(base + ARR + row * LDA + ld_q * 8) = lb[i];
        }
    };

    gload(0);
    sstore(0);
    __syncthreads();
    gload(32);

    const int NCH = FDIM / 32;  // 128 chunks
    for (int c = 0; c < NCH; c++) {
        if (c + 1 < NCH) {
            sstore((c + 1) & 1);                   // regs hold chunk c+1
            if (c + 2 < NCH) gload((c + 2) * 32);  // LDG overlaps MMA block
        }
        const __half* pA = sm[c & 1];
        const __half* pB = sm[c & 1] + ARR;

#pragma unroll
        for (int ks = 0; ks < 2; ks++) {
            int kc = ks * 16 + (lane & 3) * 2;
            uint32_t a[2][4], b[8][2];
#pragma unroll
            for (int mt = 0; mt < 2; mt++) {
                int r = wr * 32 + mt * 16 + (lane >> 2);
                a[mt][0] = *(const uint32_t*)(pA + r * LDA + kc);
                a[mt][1] = *(const uint32_t*)(pA + (r + 8) * LDA + kc);
                a[mt][2] = *(const uint32_t*)(pA + r * LDA + kc + 8);
                a[mt][3] = *(const uint32_t*)(pA + (r + 8) * LDA + kc + 8);
            }
#pragma unroll
            for (int nt = 0; nt < 8; nt++) {
                int n = wc * 64 + nt * 8 + (lane >> 2);
                b[nt][0] = *(const uint32_t*)(pB + n * LDA + kc);
                b[nt][1] = *(const uint32_t*)(pB + n * LDA + kc + 8);
            }
#pragma unroll
            for (int mt = 0; mt < 2; mt++)
#pragma unroll
                for (int nt = 0; nt < 8; nt++) mma16816(acc[mt][nt], a[mt], b[nt]);
        }
        __syncthreads();
    }

    // epilogue: +bias, sigmoid, store fp32
#pragma unroll
    for (int mt = 0; mt < 2; mt++)
#pragma unroll
        for (int nt = 0; nt < 8; nt++)
#pragma unroll
            for (int i = 0; i < 4; i++) {
                int row = mBase + wr * 32 + mt * 16 + (lane >> 2) + ((i >= 2) ? 8 : 0);
                int col = nBase + wc * 64 + nt * 8 + (lane & 3) * 2 + (i & 1);
                if (col < NINT) {
                    float v = acc[mt][nt][i] + __ldg(bias + col);
                    g_ps[(size_t)row * 512 + col] = 1.0f / (1.0f + __expf(-v));
                }
            }
}

// ============================================================================
// Kernel 3: tree — leaf_prob from ps, stored fp16
// ============================================================================
__global__ void tree_kernel(const float* guard) {
    if (guard == nullptr) return;  // warmup guard
    int row = blockIdx.x;
    int j = threadIdx.x;  // leaf 0..511
    __shared__ float sp[512];
    sp[j] = g_ps[(size_t)row * 512 + j];
    __syncthreads();
    float lp = 1.0f;
    int node = 0;
#pragma unroll
    for (int t = 0; t < 9; t++) {
        int bit = (j >> (8 - t)) & 1;
        float p = sp[node];
        lp *= bit ? p : (1.0f - p);
        node = 2 * node + 1 + bit;
    }
    g_lp[(size_t)row * 512 + j] = __float2half_rn(lp);
}

// ============================================================================
// Kernel 4: GEMM2  out = leaf_prob @ dists   (single-pass fp16)
// CTA 128x128, K=512 chunks of 32, double-buffered static smem 20KB,
// 2 CTAs/SM via launch_bounds.
// ============================================================================
__global__ void __launch_bounds__(256, 2)
gemm2_kernel(float* __restrict__ out) {
    if (out == nullptr) return;  // warmup guard
    __shared__ __half sm2[2][2 * ARR];

    int tid = threadIdx.x, lane = tid & 31, wid = tid >> 5;
    int wr = wid & 3, wc = wid >> 2;
    int mBase = blockIdx.y * 128, nBase = blockIdx.x * 128;

    float acc[2][8][4];
#pragma unroll
    for (int mt = 0; mt < 2; mt++)
#pragma unroll
        for (int nt = 0; nt < 8; nt++)
#pragma unroll
            for (int i = 0; i < 4; i++) acc[mt][nt][i] = 0.f;

    const uint4 z4 = make_uint4(0, 0, 0, 0);
    const int ld_row = tid >> 2, ld_q = tid & 3;   // 4 uint4 (=32 fp16) per 64-row slab
    uint4 raq[2], rbq[2];

    auto gload = [&](int k0) {
#pragma unroll
        for (int i = 0; i < 2; i++) {
            int row = ld_row + i * 64;
            raq[i] = *(const uint4*)(g_lp + (size_t)(mBase + row) * 512 + k0 + ld_q * 8);
            int rg = nBase + row;
            rbq[i] = (rg < KOUT) ? *(const uint4*)(g_dT + (size_t)rg * 512 + k0 + ld_q * 8) : z4;
        }
    };
    auto sstore = [&](int buf) {
        __half* base = sm2[buf];
#pragma unroll
        for (int i = 0; i < 2; i++) {
            int row = ld_row + i * 64;
            *(uint4*)(base + row * LDA + ld_q * 8)       = raq[i];
            *(uint4*)(base + ARR + row * LDA + ld_q * 8) = rbq[i];
        }
    };

    gload(0);
    sstore(0);
    __syncthreads();
    gload(32);

    const int NCH = 512 / 32;  // 16 chunks
    for (int c = 0; c < NCH; c++) {
        if (c + 1 < NCH) {
            sstore((c + 1) & 1);
            if (c + 2 < NCH) gload((c + 2) * 32);
        }
        const __half* pA = sm2[c & 1];
        const __half* pB = sm2[c & 1] + ARR;

#pragma unroll
        for (int ks = 0; ks < 2; ks++) {
            int kc = ks * 16 + (lane & 3) * 2;
            uint32_t a[2][4], b[8][2];
#pragma unroll
            for (int mt = 0; mt < 2; mt++) {
                int r = wr * 32 + mt * 16 + (lane >> 2);
                a[mt][0] = *(const uint32_t*)(pA + r * LDA + kc);
                a[mt][1] = *(const uint32_t*)(pA + (r + 8) * LDA + kc);
                a[mt][2] = *(const uint32_t*)(pA + r * LDA + kc + 8);
                a[mt][3] = *(const uint32_t*)(pA + (r + 8) * LDA + kc + 8);
            }
#pragma unroll
            for (int nt = 0; nt < 8; nt++) {
                int n = wc * 64 + nt * 8 + (lane >> 2);
                b[nt][0] = *(const uint32_t*)(pB + n * LDA + kc);
                b[nt][1] = *(const uint32_t*)(pB + n * LDA + kc + 8);
            }
#pragma unroll
            for (int mt = 0; mt < 2; mt++)
#pragma unroll
                for (int nt = 0; nt < 8; nt++) mma16816(acc[mt][nt], a[mt], b[nt]);
        }
        __syncthreads();
    }

#pragma unroll
    for (int mt = 0; mt < 2; mt++)
#pragma unroll
        for (int nt = 0; nt < 8; nt++)
#pragma unroll
            for (int i = 0; i < 4; i++) {
                int row = mBase + wr * 32 + mt * 16 + (lane >> 2) + ((i >= 2) ? 8 : 0);
                int col = nBase + wc * 64 + nt * 8 + (lane & 3) * 2 + (i & 1);
                if (col < KOUT) out[(size_t)row * KOUT + col] = acc[mt][nt][i];
            }
}

// ============================================================================
// Module preload (static ctor; warmups are null-guarded no-ops, same grids).
// All smem static; no attribute calls needed.
// ============================================================================
namespace {
struct Boot {
    Boot() {
        void* p;
        cudaGetSymbolAddress(&p, g_ps);
        cudaGetSymbolAddress(&p, g_lp);
        cudaGetSymbolAddress(&p, g_dT);
        cudaGetSymbolAddress(&p, g_xs16);
        cudaGetSymbolAddress(&p, g_W16);
        cvt_kernel<<<(BATCH * FDIM) / 2048, 256>>>(nullptr, nullptr, 0, 0);
        cvt_kernel<<<(512 * FDIM) / 2048, 256>>>(nullptr, nullptr, 0, 0);
        softmax_kernel<<<512, 256>>>(nullptr);
        gemm1_kernel<<<dim3(4, 64), 256>>>(nullptr);
        tree_kernel<<<BATCH, 512>>>(nullptr);
        gemm2_kernel<<<dim3(8, 64), 256>>>(nullptr);
        cudaDeviceSynchronize();
    }
};
Boot g_boot;
}  // namespace

// ============================================================================
extern "C" void kernel_launch(void* const* d_in, const int* in_sizes, int n_in,
                              void* d_out, int out_size) {
    (void)in_sizes; (void)n_in; (void)out_size;
    const float* xs   = (const float*)d_in[0];
    const float* W    = (const float*)d_in[1];
    const float* bias = (const float*)d_in[2];
    const float* leaf = (const float*)d_in[3];
    float* out = (float*)d_out;

    __half* xs16; cudaGetSymbolAddress((void**)&xs16, g_xs16);
    __half* w16;  cudaGetSymbolAddress((void**)&w16,  g_W16);

    cvt_kernel<<<(BATCH * FDIM) / 2048, 256>>>(xs, xs16, BATCH * FDIM, BATCH * FDIM);
    cvt_kernel<<<(512 * FDIM) / 2048, 256>>>(W, w16, NINT * FDIM, 512 * FDIM);
    softmax_kernel<<<512, 256>>>(leaf);
    gemm1_kernel<<<dim3(4, 64), 256>>>(bias);
    tree_kernel<<<BATCH, 512>>>(xs);
    gemm2_kernel<<<dim3(8, 64), 256>>>(out);
}